// round 5
// baseline (speedup 1.0000x reference)
#include <cuda_runtime.h>
#include <math.h>

// Problem constants
#define BATCH   2
#define NSEQ    2048
#define HEADS   8
#define DHEAD   64
#define DIMM    512
#define BHDIM   (BATCH*HEADS)        // 16
#define MROWS   (BATCH*NSEQ)         // 4096
#define QROWS   (BHDIM*NSEQ)         // 32768
#define TVALS   1025                 // 2*512+1
#define PLD     1028                 // padded row stride for P (mult of 4)
#define RELTLD  1088                 // padded (17*64) col count for relT
#define SCALE_F 0.125f               // 64^-0.5

// ---------------- device scratch (static globals: allocation-free) ----------
__device__ float g_Q[BHDIM * NSEQ * DHEAD];           // [bh][n][d]   8 MB
__device__ float g_K[BHDIM * NSEQ * DHEAD];           //              8 MB
__device__ float g_V[BHDIM * NSEQ * DHEAD];           //              8 MB
__device__ float g_P[(size_t)BHDIM * NSEQ * PLD];     // [bh][n][t]   ~135 MB
__device__ float g_O[BATCH * NSEQ * DIMM];            // [b][n][h*d]  8 MB
__device__ float g_relT[DHEAD * RELTLD];              // [d][t] padded, zero-filled

// ---------------- 16-FMA micro tile -----------------------------------------
__device__ __forceinline__ void fma16(float4 a, float4 b, float (&c)[4][4]) {
    c[0][0] = fmaf(a.x, b.x, c[0][0]); c[0][1] = fmaf(a.x, b.y, c[0][1]);
    c[0][2] = fmaf(a.x, b.z, c[0][2]); c[0][3] = fmaf(a.x, b.w, c[0][3]);
    c[1][0] = fmaf(a.y, b.x, c[1][0]); c[1][1] = fmaf(a.y, b.y, c[1][1]);
    c[1][2] = fmaf(a.y, b.z, c[1][2]); c[1][3] = fmaf(a.y, b.w, c[1][3]);
    c[2][0] = fmaf(a.z, b.x, c[2][0]); c[2][1] = fmaf(a.z, b.y, c[2][1]);
    c[2][2] = fmaf(a.z, b.z, c[2][2]); c[2][3] = fmaf(a.z, b.w, c[2][3]);
    c[3][0] = fmaf(a.w, b.x, c[3][0]); c[3][1] = fmaf(a.w, b.y, c[3][1]);
    c[3][2] = fmaf(a.w, b.z, c[3][2]); c[3][3] = fmaf(a.w, b.w, c[3][3]);
}

// ---------------- shared 64x64 sgemm core (BK=16, 256 threads, 4x4/thread) --
// A row-major [64, kdim] (pre-offset to block row), B row-major [kdim, >=64]
// (pre-offset to block col). Ats stored transposed with stride 68 (16B-aligned
// rows, conflict-light strided writes); Bs stored direct (coalesced).
__device__ __forceinline__ void sgemm_core(
    const float* __restrict__ A, int lda,
    const float* __restrict__ B, int ldb,
    int kdim, float (&acc)[4][4],
    float (*Ats)[68], float (*Bs)[64])
{
    const int tid = threadIdx.x;
    const int ty  = tid >> 4, tx = tid & 15;
    const int am  = tid >> 2;            // 0..63
    const int ak  = (tid & 3) << 2;      // 0,4,8,12
    const int bk  = tid >> 4;            // 0..15
    const int bn  = (tid & 15) << 2;     // 0..60

    for (int k0 = 0; k0 < kdim; k0 += 16) {
        float4 a = *(const float4*)(A + (size_t)am * lda + k0 + ak);
        Ats[ak + 0][am] = a.x; Ats[ak + 1][am] = a.y;
        Ats[ak + 2][am] = a.z; Ats[ak + 3][am] = a.w;
        *(float4*)(&Bs[bk][bn]) = *(const float4*)(B + (size_t)(k0 + bk) * ldb + bn);
        __syncthreads();
        #pragma unroll
        for (int k = 0; k < 16; k++) {
            float4 av = *(const float4*)(&Ats[k][ty << 2]);
            float4 bv = *(const float4*)(&Bs[k][tx << 2]);
            fma16(av, bv, acc);
        }
        __syncthreads();
    }
}

// ---------------- kernel 0: transpose+pad rel_emb [1025,64] -> [64,1088] ----
__global__ void __launch_bounds__(256) transpose_rel_kernel(
    const float* __restrict__ rel, float* __restrict__ relT)
{
    int idx = blockIdx.x * 256 + threadIdx.x;
    if (idx < DHEAD * RELTLD) {
        int d = idx / RELTLD;
        int t = idx % RELTLD;
        relT[idx] = (t < TVALS) ? rel[(size_t)t * DHEAD + d] : 0.0f;
    }
}

// ---------------- kernel 1: fused QKV projection -----------------------------
// C = x[4096,512] @ [Wq | Wkv]  -> scatter into Q/K/V in [bh][n][d] layout.
// grid (64, 24): y block selects 64 output cols = exactly one head slice.
__global__ void __launch_bounds__(256) gemm_qkv_kernel(
    const float* __restrict__ x,
    const float* __restrict__ Wq, const float* __restrict__ Wkv,
    float* __restrict__ Q, float* __restrict__ K, float* __restrict__ V)
{
    __shared__ float Ats[16][68];
    __shared__ float Bs[16][64];

    const int m0 = blockIdx.x << 6;
    const int c0 = blockIdx.y << 6;          // 0..1472

    const float* W; int wcol, ldw; float* out;
    if (c0 < 512)        { W = Wq;  wcol = c0;        ldw = 512;  out = Q; }
    else if (c0 < 1024)  { W = Wkv; wcol = c0 - 512;  ldw = 1024; out = K; }
    else                 { W = Wkv; wcol = c0 - 512;  ldw = 1024; out = V; }
    const int head = (c0 & 511) >> 6;

    float acc[4][4] = {};
    sgemm_core(x + (size_t)m0 * DIMM, DIMM, W + wcol, ldw, DIMM, acc, Ats, Bs);

    const int ty = threadIdx.x >> 4, tx = threadIdx.x & 15;
    #pragma unroll
    for (int ii = 0; ii < 4; ii++) {
        int r = m0 + (ty << 2) + ii;          // = b*2048 + n
        int b = r >> 11, n = r & 2047;
        size_t base = (((size_t)(b * HEADS + head)) * NSEQ + n) * DHEAD + (tx << 2);
        float4 v = make_float4(acc[ii][0], acc[ii][1], acc[ii][2], acc[ii][3]);
        *(float4*)(out + base) = v;
    }
}

// ---------------- kernel 2: P = Q @ rel_embT  (32768 x 1025 x 64) -----------
__global__ void __launch_bounds__(256) gemm_p_kernel(
    const float* __restrict__ Q, const float* __restrict__ relT,
    float* __restrict__ P)
{
    __shared__ float Ats[16][68];
    __shared__ float Bs[16][64];

    const int m0 = blockIdx.x << 6;
    const int t0 = blockIdx.y << 6;

    float acc[4][4] = {};
    sgemm_core(Q + (size_t)m0 * DHEAD, DHEAD, relT + t0, RELTLD, DHEAD, acc, Ats, Bs);

    const int ty = threadIdx.x >> 4, tx = threadIdx.x & 15;
    const int tcol = t0 + (tx << 2);
    #pragma unroll
    for (int ii = 0; ii < 4; ii++) {
        size_t base = (size_t)(m0 + (ty << 2) + ii) * PLD + tcol;
        if (tcol + 3 < TVALS) {
            float4 v = make_float4(acc[ii][0], acc[ii][1], acc[ii][2], acc[ii][3]);
            *(float4*)(P + base) = v;
        } else {
            #pragma unroll
            for (int jj = 0; jj < 4; jj++)
                if (tcol + jj < TVALS) P[base + jj] = acc[ii][jj];
        }
    }
}

// ---------------- kernel 3: flash attention with precomputed rel bias --------
// grid (N/64=32, BH=16), 256 threads, dynamic smem 68608 B.
__global__ void __launch_bounds__(256) flash_kernel(
    const float* __restrict__ Q, const float* __restrict__ K,
    const float* __restrict__ V, const float* __restrict__ P,
    float* __restrict__ O)
{
    extern __shared__ float smf[];
    float (*Qts)[68] = (float (*)[68])(smf);                 // [d][i]
    float (*Kts)[68] = (float (*)[68])(smf + 64 * 68);       // [d][j]
    float (*Pts)[68] = (float (*)[68])(smf + 2 * 64 * 68);   // [j][i]
    float (*Vs )[64] = (float (*)[64])(smf + 3 * 64 * 68);   // [j][dd]

    const int bh = blockIdx.y;
    const int n0 = blockIdx.x << 6;
    const float* Qb = Q + (size_t)bh * NSEQ * DHEAD;
    const float* Kb = K + (size_t)bh * NSEQ * DHEAD;
    const float* Vb = V + (size_t)bh * NSEQ * DHEAD;
    const float* Pb = P + (size_t)bh * NSEQ * PLD;

    const int tid  = threadIdx.x;
    const int ty   = tid >> 4, tx = tid & 15;
    const int lrow = tid >> 4;            // 0..15
    const int lc4  = (tid & 15) << 2;     // 0..60

    // Load Q tile transposed (visible after first in-loop syncthreads)
    #pragma unroll
    for (int it = 0; it < 4; it++) {
        int row = lrow + (it << 4);
        float4 v = *(const float4*)(Qb + (size_t)(n0 + row) * DHEAD + lc4);
        Qts[lc4 + 0][row] = v.x; Qts[lc4 + 1][row] = v.y;
        Qts[lc4 + 2][row] = v.z; Qts[lc4 + 3][row] = v.w;
    }

    float m_i[4], l_i[4], o_acc[4][4];
    #pragma unroll
    for (int ii = 0; ii < 4; ii++) {
        m_i[ii] = -1e30f; l_i[ii] = 0.0f;
        #pragma unroll
        for (int rr = 0; rr < 4; rr++) o_acc[ii][rr] = 0.0f;
    }

    for (int j0 = 0; j0 < NSEQ; j0 += 64) {
        // load K (transposed) and V (direct)
        #pragma unroll
        for (int it = 0; it < 4; it++) {
            int row = lrow + (it << 4);
            float4 kv = *(const float4*)(Kb + (size_t)(j0 + row) * DHEAD + lc4);
            Kts[lc4 + 0][row] = kv.x; Kts[lc4 + 1][row] = kv.y;
            Kts[lc4 + 2][row] = kv.z; Kts[lc4 + 3][row] = kv.w;
            *(float4*)(&Vs[row][lc4]) =
                *(const float4*)(Vb + (size_t)(j0 + row) * DHEAD + lc4);
        }
        __syncthreads();

        // S = Q K^T (4x4 per thread)
        float s[4][4] = {};
        #pragma unroll 8
        for (int d = 0; d < 64; d++) {
            float4 av = *(const float4*)(&Qts[d][ty << 2]);
            float4 bv = *(const float4*)(&Kts[d][tx << 2]);
            fma16(av, bv, s);
        }

        // add relative bias (gather from P), scale, track row max
        float rowmax[4] = {-1e30f, -1e30f, -1e30f, -1e30f};
        #pragma unroll
        for (int ii = 0; ii < 4; ii++) {
            int n = n0 + (ty << 2) + ii;
            const float* prow = Pb + (size_t)n * PLD;
            #pragma unroll
            for (int jj = 0; jj < 4; jj++) {
                int j = j0 + (tx << 2) + jj;
                int t = n - j;
                t = t < -512 ? -512 : (t > 512 ? 512 : t);
                float v = (s[ii][jj] + prow[t + 512]) * SCALE_F;
                s[ii][jj] = v;
                rowmax[ii] = fmaxf(rowmax[ii], v);
            }
        }
        #pragma unroll
        for (int msk = 1; msk < 16; msk <<= 1) {
            #pragma unroll
            for (int ii = 0; ii < 4; ii++)
                rowmax[ii] = fmaxf(rowmax[ii],
                                   __shfl_xor_sync(0xffffffffu, rowmax[ii], msk));
        }

        float corr[4], rs[4];
        #pragma unroll
        for (int ii = 0; ii < 4; ii++) {
            float mnew = fmaxf(m_i[ii], rowmax[ii]);
            corr[ii] = __expf(m_i[ii] - mnew);
            m_i[ii] = mnew;
            rs[ii] = 0.0f;
        }
        #pragma unroll
        for (int ii = 0; ii < 4; ii++) {
            #pragma unroll
            for (int jj = 0; jj < 4; jj++) {
                float p = __expf(s[ii][jj] - m_i[ii]);
                s[ii][jj] = p;
                rs[ii] += p;
            }
        }
        #pragma unroll
        for (int msk = 1; msk < 16; msk <<= 1) {
            #pragma unroll
            for (int ii = 0; ii < 4; ii++)
                rs[ii] += __shfl_xor_sync(0xffffffffu, rs[ii], msk);
        }
        #pragma unroll
        for (int ii = 0; ii < 4; ii++) {
            l_i[ii] = l_i[ii] * corr[ii] + rs[ii];
            #pragma unroll
            for (int rr = 0; rr < 4; rr++) o_acc[ii][rr] *= corr[ii];
        }

        // stage P transposed into smem for PV GEMM
        #pragma unroll
        for (int jj = 0; jj < 4; jj++) {
            float4 v = make_float4(s[0][jj], s[1][jj], s[2][jj], s[3][jj]);
            *(float4*)(&Pts[(tx << 2) + jj][ty << 2]) = v;
        }
        __syncthreads();

        // O += P V
        #pragma unroll 8
        for (int j = 0; j < 64; j++) {
            float4 av = *(const float4*)(&Pts[j][ty << 2]);
            float4 bv = *(const float4*)(&Vs[j][tx << 2]);
            fma16(av, bv, o_acc);
        }
        __syncthreads();
    }

    // epilogue: normalize and write in [b][n][h*64+dd] layout
    const int b = bh >> 3, head = bh & 7;
    #pragma unroll
    for (int ii = 0; ii < 4; ii++) {
        int n = n0 + (ty << 2) + ii;
        float inv = 1.0f / l_i[ii];
        size_t base = ((size_t)(b * NSEQ + n)) * DIMM + (head << 6) + (tx << 2);
        float4 v = make_float4(o_acc[ii][0] * inv, o_acc[ii][1] * inv,
                               o_acc[ii][2] * inv, o_acc[ii][3] * inv);
        *(float4*)(O + base) = v;
    }
}

// ---------------- kernel 4: output projection + bias -------------------------
__global__ void __launch_bounds__(256) gemm_out_kernel(
    const float* __restrict__ O, const float* __restrict__ Wo,
    const float* __restrict__ bo, float* __restrict__ out)
{
    __shared__ float Ats[16][68];
    __shared__ float Bs[16][64];

    const int m0 = blockIdx.x << 6;
    const int n0 = blockIdx.y << 6;

    float acc[4][4] = {};
    sgemm_core(O + (size_t)m0 * DIMM, DIMM, Wo + n0, DIMM, DIMM, acc, Ats, Bs);

    const int ty = threadIdx.x >> 4, tx = threadIdx.x & 15;
    const int col = n0 + (tx << 2);
    float4 bias = *(const float4*)(bo + col);
    #pragma unroll
    for (int ii = 0; ii < 4; ii++) {
        size_t base = (size_t)(m0 + (ty << 2) + ii) * DIMM + col;
        float4 v = make_float4(acc[ii][0] + bias.x, acc[ii][1] + bias.y,
                               acc[ii][2] + bias.z, acc[ii][3] + bias.w);
        *(float4*)(out + base) = v;
    }
}

// ---------------- launch ------------------------------------------------------
extern "C" void kernel_launch(void* const* d_in, const int* in_sizes, int n_in,
                              void* d_out, int out_size)
{
    const float* x    = (const float*)d_in[0];
    const float* Wq   = (const float*)d_in[1];
    const float* Wkv  = (const float*)d_in[2];
    const float* Wo   = (const float*)d_in[3];
    const float* bo   = (const float*)d_in[4];
    const float* rel  = (const float*)d_in[5];
    float* out = (float*)d_out;

    float *Qp, *Kp, *Vp, *Pp, *Op, *rTp;
    cudaGetSymbolAddress((void**)&Qp,  g_Q);
    cudaGetSymbolAddress((void**)&Kp,  g_K);
    cudaGetSymbolAddress((void**)&Vp,  g_V);
    cudaGetSymbolAddress((void**)&Pp,  g_P);
    cudaGetSymbolAddress((void**)&Op,  g_O);
    cudaGetSymbolAddress((void**)&rTp, g_relT);

    // flash kernel needs 68.6 KB dynamic smem (> 48 KB default cap)
    cudaFuncSetAttribute(flash_kernel,
                         cudaFuncAttributeMaxDynamicSharedMemorySize, 69632);

    transpose_rel_kernel<<<(DHEAD * RELTLD + 255) / 256, 256>>>(rel, rTp);
    gemm_qkv_kernel<<<dim3(MROWS / 64, 24), 256>>>(x, Wq, Wkv, Qp, Kp, Vp);
    gemm_p_kernel<<<dim3(QROWS / 64, 17), 256>>>(Qp, rTp, Pp);
    flash_kernel<<<dim3(NSEQ / 64, BHDIM), 256, 68608>>>(Qp, Kp, Vp, Pp, Op);
    gemm_out_kernel<<<dim3(MROWS / 64, DIMM / 64), 256>>>(Op, Wo, bo, out);
}

// round 6
// speedup vs baseline: 1.1182x; 1.1182x over previous
#include <cuda_runtime.h>
#include <math.h>

// Problem constants
#define BATCH   2
#define NSEQ    2048
#define HEADS   8
#define DHEAD   64
#define DIMM    512
#define BHDIM   (BATCH*HEADS)        // 16
#define MROWS   (BATCH*NSEQ)         // 4096
#define QROWS   (BHDIM*NSEQ)         // 32768
#define TVALS   1025                 // 2*512+1
#define PLD     1028                 // padded row stride for P (mult of 4)
#define RELTLD  1088                 // padded (17*64) col count for relT
#define SCALE_F 0.125f               // 64^-0.5

typedef unsigned long long u64;

// ---------------- device scratch (static globals: allocation-free) ----------
__device__ float g_Q[BHDIM * NSEQ * DHEAD];           // [bh][n][d]   8 MB
__device__ float g_K[BHDIM * NSEQ * DHEAD];           //              8 MB
__device__ float g_V[BHDIM * NSEQ * DHEAD];           //              8 MB
__device__ float g_P[(size_t)BHDIM * NSEQ * PLD];     // [bh][n][t]   ~135 MB
__device__ float g_O[BATCH * NSEQ * DIMM];            // [b][n][h*d]  8 MB
__device__ float g_relT[DHEAD * RELTLD];              // [d][t] padded, zero-filled

// ---------------- packed f32x2 primitives (B300: 2x fp32 FMA rate) ----------
__device__ __forceinline__ u64 pack2(float lo, float hi) {
    u64 r; asm("mov.b64 %0, {%1, %2};" : "=l"(r) : "f"(lo), "f"(hi)); return r;
}
__device__ __forceinline__ u64 dup2(float v) {
    u64 r; asm("mov.b64 %0, {%1, %1};" : "=l"(r) : "f"(v)); return r;
}
__device__ __forceinline__ void unpack2(u64 v, float& lo, float& hi) {
    asm("mov.b64 {%0, %1}, %2;" : "=f"(lo), "=f"(hi) : "l"(v));
}
__device__ __forceinline__ void fma2(u64& d, u64 a, u64 b) {
    asm("fma.rn.f32x2 %0, %1, %2, %0;" : "+l"(d) : "l"(a), "l"(b));
}
__device__ __forceinline__ void mul2(u64& d, u64 a) {
    asm("mul.rn.f32x2 %0, %0, %1;" : "+l"(d) : "l"(a));
}

// 16-MAC micro tile on packed pairs: c[ii][p], p=0 -> (b.x,b.y), p=1 -> (b.z,b.w)
__device__ __forceinline__ void fma16_x2(float4 a, float4 b, u64 (&c)[4][2]) {
    u64 b01 = pack2(b.x, b.y), b23 = pack2(b.z, b.w);
    u64 a0 = dup2(a.x), a1 = dup2(a.y), a2 = dup2(a.z), a3 = dup2(a.w);
    fma2(c[0][0], a0, b01); fma2(c[0][1], a0, b23);
    fma2(c[1][0], a1, b01); fma2(c[1][1], a1, b23);
    fma2(c[2][0], a2, b01); fma2(c[2][1], a2, b23);
    fma2(c[3][0], a3, b01); fma2(c[3][1], a3, b23);
}

// ---------------- shared 64x64 sgemm core (BK=16, 256 thr, 4x4/thread) ------
// Software-pipelined: global chunk k+16 loads issue while computing chunk k.
__device__ __forceinline__ void sgemm_core(
    const float* __restrict__ A, int lda,
    const float* __restrict__ B, int ldb,
    int kdim, u64 (&acc)[4][2],
    float (*Ats)[68], float (*Bs)[64])
{
    const int tid = threadIdx.x;
    const int ty  = tid >> 4, tx = tid & 15;
    const int am  = tid >> 2;            // 0..63
    const int ak  = (tid & 3) << 2;      // 0,4,8,12
    const int bk  = tid >> 4;            // 0..15
    const int bn  = (tid & 15) << 2;     // 0..60

    float4 a  = *(const float4*)(A + (size_t)am * lda + ak);
    float4 bg = *(const float4*)(B + (size_t)bk * ldb + bn);

    for (int k0 = 0; k0 < kdim; k0 += 16) {
        Ats[ak + 0][am] = a.x; Ats[ak + 1][am] = a.y;
        Ats[ak + 2][am] = a.z; Ats[ak + 3][am] = a.w;
        *(float4*)(&Bs[bk][bn]) = bg;
        __syncthreads();
        if (k0 + 16 < kdim) {   // prefetch next chunk (hidden under FFMA block)
            a  = *(const float4*)(A + (size_t)am * lda + k0 + 16 + ak);
            bg = *(const float4*)(B + (size_t)(k0 + 16 + bk) * ldb + bn);
        }
        #pragma unroll
        for (int k = 0; k < 16; k++) {
            float4 av = *(const float4*)(&Ats[k][ty << 2]);
            float4 bv = *(const float4*)(&Bs[k][tx << 2]);
            fma16_x2(av, bv, acc);
        }
        __syncthreads();
    }
}

// ---------------- kernel 0: transpose+pad rel_emb [1025,64] -> [64,1088] ----
__global__ void __launch_bounds__(256) transpose_rel_kernel(
    const float* __restrict__ rel, float* __restrict__ relT)
{
    int idx = blockIdx.x * 256 + threadIdx.x;
    if (idx < DHEAD * RELTLD) {
        int d = idx / RELTLD;
        int t = idx % RELTLD;
        relT[idx] = (t < TVALS) ? rel[(size_t)t * DHEAD + d] : 0.0f;
    }
}

// ---------------- kernel 1: fused QKV projection -----------------------------
__global__ void __launch_bounds__(256) gemm_qkv_kernel(
    const float* __restrict__ x,
    const float* __restrict__ Wq, const float* __restrict__ Wkv,
    float* __restrict__ Q, float* __restrict__ K, float* __restrict__ V)
{
    __shared__ float Ats[16][68];
    __shared__ float Bs[16][64];

    const int m0 = blockIdx.x << 6;
    const int c0 = blockIdx.y << 6;          // 0..1472

    const float* W; int wcol, ldw; float* out;
    if (c0 < 512)        { W = Wq;  wcol = c0;        ldw = 512;  out = Q; }
    else if (c0 < 1024)  { W = Wkv; wcol = c0 - 512;  ldw = 1024; out = K; }
    else                 { W = Wkv; wcol = c0 - 512;  ldw = 1024; out = V; }
    const int head = (c0 & 511) >> 6;

    u64 acc[4][2] = {};
    sgemm_core(x + (size_t)m0 * DIMM, DIMM, W + wcol, ldw, DIMM, acc, Ats, Bs);

    const int ty = threadIdx.x >> 4, tx = threadIdx.x & 15;
    #pragma unroll
    for (int ii = 0; ii < 4; ii++) {
        int r = m0 + (ty << 2) + ii;          // = b*2048 + n
        int b = r >> 11, n = r & 2047;
        size_t base = (((size_t)(b * HEADS + head)) * NSEQ + n) * DHEAD + (tx << 2);
        float4 v;
        unpack2(acc[ii][0], v.x, v.y);
        unpack2(acc[ii][1], v.z, v.w);
        *(float4*)(out + base) = v;
    }
}

// ---------------- kernel 2: P = Q @ rel_embT  (32768 x 1025 x 64) -----------
__global__ void __launch_bounds__(256) gemm_p_kernel(
    const float* __restrict__ Q, const float* __restrict__ relT,
    float* __restrict__ P)
{
    __shared__ float Ats[16][68];
    __shared__ float Bs[16][64];

    const int m0 = blockIdx.x << 6;
    const int t0 = blockIdx.y << 6;

    u64 acc[4][2] = {};
    sgemm_core(Q + (size_t)m0 * DHEAD, DHEAD, relT + t0, RELTLD, DHEAD, acc, Ats, Bs);

    const int ty = threadIdx.x >> 4, tx = threadIdx.x & 15;
    const int tcol = t0 + (tx << 2);
    #pragma unroll
    for (int ii = 0; ii < 4; ii++) {
        size_t base = (size_t)(m0 + (ty << 2) + ii) * PLD + tcol;
        float4 v;
        unpack2(acc[ii][0], v.x, v.y);
        unpack2(acc[ii][1], v.z, v.w);
        if (tcol + 3 < TVALS) {
            *(float4*)(P + base) = v;
        } else {
            float tmp[4] = {v.x, v.y, v.z, v.w};
            #pragma unroll
            for (int jj = 0; jj < 4; jj++)
                if (tcol + jj < TVALS) P[base + jj] = tmp[jj];
        }
    }
}

// ---------------- kernel 3: flash attention with precomputed rel bias --------
// grid (N/64=32, BH=16), 256 threads, dynamic smem 68608 B.
// Register prefetch: P-bias gather before QK; next K/V tile during PV epilogue.
__global__ void __launch_bounds__(256, 2) flash_kernel(
    const float* __restrict__ Q, const float* __restrict__ K,
    const float* __restrict__ V, const float* __restrict__ P,
    float* __restrict__ O)
{
    extern __shared__ float smf[];
    float (*Qts)[68] = (float (*)[68])(smf);                 // [d][i]
    float (*Kts)[68] = (float (*)[68])(smf + 64 * 68);       // [d][j]
    float (*Pts)[68] = (float (*)[68])(smf + 2 * 64 * 68);   // [j][i]
    float (*Vs )[64] = (float (*)[64])(smf + 3 * 64 * 68);   // [j][dd]

    const int bh = blockIdx.y;
    const int n0 = blockIdx.x << 6;
    const float* Qb = Q + (size_t)bh * NSEQ * DHEAD;
    const float* Kb = K + (size_t)bh * NSEQ * DHEAD;
    const float* Vb = V + (size_t)bh * NSEQ * DHEAD;
    const float* Pb = P + (size_t)bh * NSEQ * PLD;

    const int tid  = threadIdx.x;
    const int ty   = tid >> 4, tx = tid & 15;
    const int lrow = tid >> 4;            // 0..15
    const int lc4  = (tid & 15) << 2;     // 0..60

    // Load Q tile transposed (visible after first in-loop syncthreads)
    #pragma unroll
    for (int it = 0; it < 4; it++) {
        int row = lrow + (it << 4);
        float4 v = *(const float4*)(Qb + (size_t)(n0 + row) * DHEAD + lc4);
        Qts[lc4 + 0][row] = v.x; Qts[lc4 + 1][row] = v.y;
        Qts[lc4 + 2][row] = v.z; Qts[lc4 + 3][row] = v.w;
    }

    // Prefetch K/V tile 0 into registers
    float4 kp[4], vp[4];
    #pragma unroll
    for (int it = 0; it < 4; it++) {
        int row = lrow + (it << 4);
        kp[it] = *(const float4*)(Kb + (size_t)row * DHEAD + lc4);
        vp[it] = *(const float4*)(Vb + (size_t)row * DHEAD + lc4);
    }

    float m_i[4], l_i[4];
    u64 o2[4][2];
    #pragma unroll
    for (int ii = 0; ii < 4; ii++) {
        m_i[ii] = -1e30f; l_i[ii] = 0.0f;
        o2[ii][0] = 0ull; o2[ii][1] = 0ull;
    }

    for (int jt = 0; jt < NSEQ / 64; jt++) {
        const int j0 = jt << 6;

        // stage prefetched K (transposed) and V (direct)
        #pragma unroll
        for (int it = 0; it < 4; it++) {
            int row = lrow + (it << 4);
            Kts[lc4 + 0][row] = kp[it].x; Kts[lc4 + 1][row] = kp[it].y;
            Kts[lc4 + 2][row] = kp[it].z; Kts[lc4 + 3][row] = kp[it].w;
            *(float4*)(&Vs[row][lc4]) = vp[it];
        }
        __syncthreads();                                      // (a)

        // prefetch P bias values for this tile (used after QK)
        float pf[4][4];
        #pragma unroll
        for (int ii = 0; ii < 4; ii++) {
            int n = n0 + (ty << 2) + ii;
            const float* prow = Pb + (size_t)n * PLD;
            #pragma unroll
            for (int jj = 0; jj < 4; jj++) {
                int t = n - (j0 + (tx << 2) + jj);
                t = t < -512 ? -512 : (t > 512 ? 512 : t);
                pf[ii][jj] = prow[t + 512];
            }
        }

        // S = Q K^T (packed pairs)
        u64 s2[4][2];
        #pragma unroll
        for (int ii = 0; ii < 4; ii++) { s2[ii][0] = 0ull; s2[ii][1] = 0ull; }
        #pragma unroll 8
        for (int d = 0; d < 64; d++) {
            float4 av = *(const float4*)(&Qts[d][ty << 2]);
            float4 bv = *(const float4*)(&Kts[d][tx << 2]);
            fma16_x2(av, bv, s2);
        }

        // unpack, add bias, scale, row max
        float s[4][4];
        float rowmax[4];
        #pragma unroll
        for (int ii = 0; ii < 4; ii++) {
            unpack2(s2[ii][0], s[ii][0], s[ii][1]);
            unpack2(s2[ii][1], s[ii][2], s[ii][3]);
            rowmax[ii] = -1e30f;
            #pragma unroll
            for (int jj = 0; jj < 4; jj++) {
                float v = (s[ii][jj] + pf[ii][jj]) * SCALE_F;
                s[ii][jj] = v;
                rowmax[ii] = fmaxf(rowmax[ii], v);
            }
        }
        #pragma unroll
        for (int msk = 1; msk < 16; msk <<= 1) {
            #pragma unroll
            for (int ii = 0; ii < 4; ii++)
                rowmax[ii] = fmaxf(rowmax[ii],
                                   __shfl_xor_sync(0xffffffffu, rowmax[ii], msk));
        }

        float corr[4], rs[4];
        #pragma unroll
        for (int ii = 0; ii < 4; ii++) {
            float mnew = fmaxf(m_i[ii], rowmax[ii]);
            corr[ii] = __expf(m_i[ii] - mnew);
            m_i[ii] = mnew;
            rs[ii] = 0.0f;
        }
        #pragma unroll
        for (int ii = 0; ii < 4; ii++) {
            #pragma unroll
            for (int jj = 0; jj < 4; jj++) {
                float p = __expf(s[ii][jj] - m_i[ii]);
                s[ii][jj] = p;
                rs[ii] += p;
            }
        }
        #pragma unroll
        for (int msk = 1; msk < 16; msk <<= 1) {
            #pragma unroll
            for (int ii = 0; ii < 4; ii++)
                rs[ii] += __shfl_xor_sync(0xffffffffu, rs[ii], msk);
        }
        #pragma unroll
        for (int ii = 0; ii < 4; ii++) {
            l_i[ii] = l_i[ii] * corr[ii] + rs[ii];
            u64 c2 = dup2(corr[ii]);
            mul2(o2[ii][0], c2);
            mul2(o2[ii][1], c2);
        }

        // stage P transposed into smem for PV GEMM
        #pragma unroll
        for (int jj = 0; jj < 4; jj++) {
            float4 v = make_float4(s[0][jj], s[1][jj], s[2][jj], s[3][jj]);
            *(float4*)(&Pts[(tx << 2) + jj][ty << 2]) = v;
        }
        __syncthreads();                                      // (b)

        // prefetch next K/V tile (latency hidden under PV compute)
        {
            int jn = (jt + 1 < NSEQ / 64 ? jt + 1 : jt) << 6;
            #pragma unroll
            for (int it = 0; it < 4; it++) {
                int row = lrow + (it << 4);
                kp[it] = *(const float4*)(Kb + (size_t)(jn + row) * DHEAD + lc4);
                vp[it] = *(const float4*)(Vb + (size_t)(jn + row) * DHEAD + lc4);
            }
        }

        // O += P V (packed pairs)
        #pragma unroll 8
        for (int j = 0; j < 64; j++) {
            float4 av = *(const float4*)(&Pts[j][ty << 2]);
            float4 bv = *(const float4*)(&Vs[j][tx << 2]);
            fma16_x2(av, bv, o2);
        }
        __syncthreads();                                      // (c)
    }

    // epilogue: normalize and write in [b][n][h*64+dd] layout
    const int b = bh >> 3, head = bh & 7;
    #pragma unroll
    for (int ii = 0; ii < 4; ii++) {
        int n = n0 + (ty << 2) + ii;
        float inv = 1.0f / l_i[ii];
        size_t base = ((size_t)(b * NSEQ + n)) * DIMM + (head << 6) + (tx << 2);
        float4 v;
        unpack2(o2[ii][0], v.x, v.y);
        unpack2(o2[ii][1], v.z, v.w);
        v.x *= inv; v.y *= inv; v.z *= inv; v.w *= inv;
        *(float4*)(O + base) = v;
    }
}

// ---------------- kernel 4: output projection + bias -------------------------
__global__ void __launch_bounds__(256) gemm_out_kernel(
    const float* __restrict__ O, const float* __restrict__ Wo,
    const float* __restrict__ bo, float* __restrict__ out)
{
    __shared__ float Ats[16][68];
    __shared__ float Bs[16][64];

    const int m0 = blockIdx.x << 6;
    const int n0 = blockIdx.y << 6;

    u64 acc[4][2] = {};
    sgemm_core(O + (size_t)m0 * DIMM, DIMM, Wo + n0, DIMM, DIMM, acc, Ats, Bs);

    const int ty = threadIdx.x >> 4, tx = threadIdx.x & 15;
    const int col = n0 + (tx << 2);
    float4 bias = *(const float4*)(bo + col);
    #pragma unroll
    for (int ii = 0; ii < 4; ii++) {
        size_t base = (size_t)(m0 + (ty << 2) + ii) * DIMM + col;
        float4 v;
        unpack2(acc[ii][0], v.x, v.y);
        unpack2(acc[ii][1], v.z, v.w);
        v.x += bias.x; v.y += bias.y; v.z += bias.z; v.w += bias.w;
        *(float4*)(out + base) = v;
    }
}

// ---------------- launch ------------------------------------------------------
extern "C" void kernel_launch(void* const* d_in, const int* in_sizes, int n_in,
                              void* d_out, int out_size)
{
    const float* x    = (const float*)d_in[0];
    const float* Wq   = (const float*)d_in[1];
    const float* Wkv  = (const float*)d_in[2];
    const float* Wo   = (const float*)d_in[3];
    const float* bo   = (const float*)d_in[4];
    const float* rel  = (const float*)d_in[5];
    float* out = (float*)d_out;

    float *Qp, *Kp, *Vp, *Pp, *Op, *rTp;
    cudaGetSymbolAddress((void**)&Qp,  g_Q);
    cudaGetSymbolAddress((void**)&Kp,  g_K);
    cudaGetSymbolAddress((void**)&Vp,  g_V);
    cudaGetSymbolAddress((void**)&Pp,  g_P);
    cudaGetSymbolAddress((void**)&Op,  g_O);
    cudaGetSymbolAddress((void**)&rTp, g_relT);

    cudaFuncSetAttribute(flash_kernel,
                         cudaFuncAttributeMaxDynamicSharedMemorySize, 69632);

    transpose_rel_kernel<<<(DHEAD * RELTLD + 255) / 256, 256>>>(rel, rTp);
    gemm_qkv_kernel<<<dim3(MROWS / 64, 24), 256>>>(x, Wq, Wkv, Qp, Kp, Vp);
    gemm_p_kernel<<<dim3(QROWS / 64, 17), 256>>>(Qp, rTp, Pp);
    flash_kernel<<<dim3(NSEQ / 64, BHDIM), 256, 68608>>>(Qp, Kp, Vp, Pp, Op);
    gemm_out_kernel<<<dim3(MROWS / 64, DIMM / 64), 256>>>(Op, Wo, bo, out);
}

// round 7
// speedup vs baseline: 1.2519x; 1.1195x over previous
#include <cuda_runtime.h>
#include <math.h>

// Problem constants
#define BATCH   2
#define NSEQ    2048
#define HEADS   8
#define DHEAD   64
#define DIMM    512
#define BHDIM   (BATCH*HEADS)        // 16
#define MROWS   (BATCH*NSEQ)         // 4096
#define QROWS   (BHDIM*NSEQ)         // 32768
#define TVALS   1025                 // 2*512+1
#define PLD     1028                 // padded row stride for P
#define RELTLD  1152                 // padded relT cols (9 tiles of 128)
#define SCALE_F 0.125f
#define QT_BH   (DHEAD*NSEQ)         // 131072: per-bh stride of [d][n] layout

typedef unsigned long long u64;

// ---------------- device scratch ---------------------------------------------
__device__ float g_Q [QROWS * DHEAD];                 // [bh][n][d] (scaled) for gemm_p
__device__ float g_Qt[BHDIM * DHEAD * NSEQ];          // [bh][d][n] (scaled) for flash
__device__ float g_Kt[BHDIM * DHEAD * NSEQ];          // [bh][d][n]
__device__ float g_V [QROWS * DHEAD];                 // [bh][n][d]
__device__ float g_P [(size_t)QROWS * PLD];           // [bh*n][t] (pre-scaled)
__device__ float g_O [MROWS * DIMM];                  // [b*n][h*d]
__device__ float g_relT[DHEAD * RELTLD];              // [d][t] zero-padded

// ---------------- packed f32x2 primitives ------------------------------------
__device__ __forceinline__ u64 pack2(float lo, float hi) {
    u64 r; asm("mov.b64 %0, {%1, %2};" : "=l"(r) : "f"(lo), "f"(hi)); return r;
}
__device__ __forceinline__ u64 dup2(float v) {
    u64 r; asm("mov.b64 %0, {%1, %1};" : "=l"(r) : "f"(v)); return r;
}
__device__ __forceinline__ void unpack2(u64 v, float& lo, float& hi) {
    asm("mov.b64 {%0, %1}, %2;" : "=f"(lo), "=f"(hi) : "l"(v));
}
__device__ __forceinline__ void fma2(u64& d, u64 a, u64 b) {
    asm("fma.rn.f32x2 %0, %1, %2, %0;" : "+l"(d) : "l"(a), "l"(b));
}
__device__ __forceinline__ void mul2(u64& d, u64 a) {
    asm("mul.rn.f32x2 %0, %0, %1;" : "+l"(d) : "l"(a));
}

// 8x8 micro tile: 32 fma2 = 64 MACs on 16 loaded floats
__device__ __forceinline__ void fma8x8(float4 a0, float4 a1,
                                       float4 b0, float4 b1, u64 (&c)[8][4]) {
    u64 p0 = pack2(b0.x, b0.y), p1 = pack2(b0.z, b0.w);
    u64 p2 = pack2(b1.x, b1.y), p3 = pack2(b1.z, b1.w);
    float as[8] = {a0.x, a0.y, a0.z, a0.w, a1.x, a1.y, a1.z, a1.w};
    #pragma unroll
    for (int ii = 0; ii < 8; ii++) {
        u64 ad = dup2(as[ii]);
        fma2(c[ii][0], ad, p0); fma2(c[ii][1], ad, p1);
        fma2(c[ii][2], ad, p2); fma2(c[ii][3], ad, p3);
    }
}

// 8x4 micro tile (for flash PV): 16 fma2 = 32 MACs
__device__ __forceinline__ void fma8x4(float4 a0, float4 a1, float4 b,
                                       u64 (&c)[8][2]) {
    u64 p0 = pack2(b.x, b.y), p1 = pack2(b.z, b.w);
    float as[8] = {a0.x, a0.y, a0.z, a0.w, a1.x, a1.y, a1.z, a1.w};
    #pragma unroll
    for (int ii = 0; ii < 8; ii++) {
        u64 ad = dup2(as[ii]);
        fma2(c[ii][0], ad, p0); fma2(c[ii][1], ad, p1);
    }
}

__device__ __forceinline__ void unpack_acc(const u64 (&acc)[8][4], float (&s)[8][8]) {
    #pragma unroll
    for (int ii = 0; ii < 8; ii++)
        #pragma unroll
        for (int p = 0; p < 4; p++)
            unpack2(acc[ii][p], s[ii][2*p], s[ii][2*p+1]);
}

// ---------------- 128x128 sgemm core (BK=16, 256 thr, 8x8/thread) ------------
__device__ __forceinline__ void sgemm128(
    const float* __restrict__ A, int lda,
    const float* __restrict__ B, int ldb,
    int kdim, u64 (&acc)[8][4],
    float (*Ats)[128], float (*Bs)[128])
{
    const int tid = threadIdx.x;
    const int ty  = tid >> 4, tx = tid & 15;
    const int ar  = tid >> 1;            // 0..127
    const int ak  = (tid & 1) << 3;      // 0 or 8
    const int br0 = tid >> 5;            // 0..7
    const int bc  = (tid & 31) << 2;     // 0..124

    float4 a0 = *(const float4*)(A + (size_t)ar * lda + ak);
    float4 a1 = *(const float4*)(A + (size_t)ar * lda + ak + 4);
    float4 b0 = *(const float4*)(B + (size_t)br0 * ldb + bc);
    float4 b1 = *(const float4*)(B + (size_t)(br0 + 8) * ldb + bc);

    for (int k0 = 0; k0 < kdim; k0 += 16) {
        Ats[ak + 0][ar] = a0.x; Ats[ak + 1][ar] = a0.y;
        Ats[ak + 2][ar] = a0.z; Ats[ak + 3][ar] = a0.w;
        Ats[ak + 4][ar] = a1.x; Ats[ak + 5][ar] = a1.y;
        Ats[ak + 6][ar] = a1.z; Ats[ak + 7][ar] = a1.w;
        *(float4*)(&Bs[br0][bc])     = b0;
        *(float4*)(&Bs[br0 + 8][bc]) = b1;
        __syncthreads();
        if (k0 + 16 < kdim) {
            a0 = *(const float4*)(A + (size_t)ar * lda + k0 + 16 + ak);
            a1 = *(const float4*)(A + (size_t)ar * lda + k0 + 16 + ak + 4);
            b0 = *(const float4*)(B + (size_t)(k0 + 16 + br0) * ldb + bc);
            b1 = *(const float4*)(B + (size_t)(k0 + 24 + br0) * ldb + bc);
        }
        #pragma unroll
        for (int kk = 0; kk < 16; kk++) {
            float4 av0 = *(const float4*)(&Ats[kk][ty << 3]);
            float4 av1 = *(const float4*)(&Ats[kk][(ty << 3) + 4]);
            float4 bv0 = *(const float4*)(&Bs[kk][tx << 3]);
            float4 bv1 = *(const float4*)(&Bs[kk][(tx << 3) + 4]);
            fma8x8(av0, av1, bv0, bv1, acc);
        }
        __syncthreads();
    }
}

// ---------------- kernel 0: transpose+pad rel_emb ----------------------------
__global__ void __launch_bounds__(256) transpose_rel_kernel(
    const float* __restrict__ rel, float* __restrict__ relT)
{
    int idx = blockIdx.x * 256 + threadIdx.x;
    if (idx < DHEAD * RELTLD) {
        int d = idx / RELTLD;
        int t = idx % RELTLD;
        relT[idx] = (t < TVALS) ? rel[(size_t)t * DHEAD + d] : 0.0f;
    }
}

// ---------------- kernel 1: fused QKV projection (128x128 tiles) -------------
// grid (32, 12): y*128 in [0,512)=Q (scaled, two layouts), [512,1024)=Kt, rest V
__global__ void __launch_bounds__(256, 2) gemm_qkv_kernel(
    const float* __restrict__ x,
    const float* __restrict__ Wq, const float* __restrict__ Wkv,
    float* __restrict__ Q, float* __restrict__ Qt,
    float* __restrict__ Kt, float* __restrict__ V)
{
    __shared__ float Ats[16][128];
    __shared__ float Bs[16][128];

    const int m0 = blockIdx.x << 7;
    const int c0 = blockIdx.y << 7;          // 0..1408

    const float* W; int wcol, ldw;
    if (c0 < 512) { W = Wq;  wcol = c0;       ldw = 512;  }
    else          { W = Wkv; wcol = c0 - 512; ldw = 1024; }

    u64 acc[8][4] = {};
    sgemm128(x + (size_t)m0 * DIMM, DIMM, W + wcol, ldw, DIMM, acc, Ats, Bs);

    float s[8][8];
    unpack_acc(acc, s);

    const int ty = threadIdx.x >> 4, tx = threadIdx.x & 15;
    const int colb = c0 + (tx << 3);          // base col of this thread (8 wide)

    if (c0 < 512) {
        // Q: scale, write [bh][n][d] and [bh][d][n]
        #pragma unroll
        for (int ii = 0; ii < 8; ii++)
            #pragma unroll
            for (int jj = 0; jj < 8; jj++) s[ii][jj] *= SCALE_F;
        #pragma unroll
        for (int ii = 0; ii < 8; ii++) {
            int r = m0 + (ty << 3) + ii;
            int b = r >> 11, n = r & 2047;
            int head = (colb & 511) >> 6, dl = colb & 63;
            size_t base = (((size_t)(b * HEADS + head)) * NSEQ + n) * DHEAD + dl;
            *(float4*)(Q + base)     = make_float4(s[ii][0], s[ii][1], s[ii][2], s[ii][3]);
            *(float4*)(Q + base + 4) = make_float4(s[ii][4], s[ii][5], s[ii][6], s[ii][7]);
        }
        #pragma unroll
        for (int jj = 0; jj < 8; jj++) {
            int col = colb + jj;
            int head = (col & 511) >> 6, dl = col & 63;
            #pragma unroll
            for (int g = 0; g < 2; g++) {
                int r = m0 + (ty << 3) + g * 4;
                int b = r >> 11, n = r & 2047;
                size_t base = (size_t)(b * HEADS + head) * QT_BH + (size_t)dl * NSEQ + n;
                *(float4*)(Qt + base) = make_float4(s[g*4+0][jj], s[g*4+1][jj],
                                                    s[g*4+2][jj], s[g*4+3][jj]);
            }
        }
    } else if (c0 < 1024) {
        // K: write transposed [bh][d][n]
        #pragma unroll
        for (int jj = 0; jj < 8; jj++) {
            int col = colb + jj;
            int head = (col & 511) >> 6, dl = col & 63;
            #pragma unroll
            for (int g = 0; g < 2; g++) {
                int r = m0 + (ty << 3) + g * 4;
                int b = r >> 11, n = r & 2047;
                size_t base = (size_t)(b * HEADS + head) * QT_BH + (size_t)dl * NSEQ + n;
                *(float4*)(Kt + base) = make_float4(s[g*4+0][jj], s[g*4+1][jj],
                                                    s[g*4+2][jj], s[g*4+3][jj]);
            }
        }
    } else {
        // V: normal [bh][n][d]
        #pragma unroll
        for (int ii = 0; ii < 8; ii++) {
            int r = m0 + (ty << 3) + ii;
            int b = r >> 11, n = r & 2047;
            int head = (colb & 511) >> 6, dl = colb & 63;
            size_t base = (((size_t)(b * HEADS + head)) * NSEQ + n) * DHEAD + dl;
            *(float4*)(V + base)     = make_float4(s[ii][0], s[ii][1], s[ii][2], s[ii][3]);
            *(float4*)(V + base + 4) = make_float4(s[ii][4], s[ii][5], s[ii][6], s[ii][7]);
        }
    }
}

// ---------------- kernel 2: P = Qscaled @ relT  (32768 x 1025 x 64) ----------
__global__ void __launch_bounds__(256, 2) gemm_p_kernel(
    const float* __restrict__ Q, const float* __restrict__ relT,
    float* __restrict__ P)
{
    __shared__ float Ats[16][128];
    __shared__ float Bs[16][128];

    const int m0 = blockIdx.x << 7;
    const int t0 = blockIdx.y << 7;

    u64 acc[8][4] = {};
    sgemm128(Q + (size_t)m0 * DHEAD, DHEAD, relT + t0, RELTLD, DHEAD, acc, Ats, Bs);

    float s[8][8];
    unpack_acc(acc, s);

    const int ty = threadIdx.x >> 4, tx = threadIdx.x & 15;
    const int colb = t0 + (tx << 3);
    const bool full = (t0 + 127) < TVALS;

    #pragma unroll
    for (int ii = 0; ii < 8; ii++) {
        size_t base = (size_t)(m0 + (ty << 3) + ii) * PLD + colb;
        if (full) {
            *(float4*)(P + base)     = make_float4(s[ii][0], s[ii][1], s[ii][2], s[ii][3]);
            *(float4*)(P + base + 4) = make_float4(s[ii][4], s[ii][5], s[ii][6], s[ii][7]);
        } else {
            #pragma unroll
            for (int jj = 0; jj < 8; jj++)
                if (colb + jj < TVALS) P[base + jj] = s[ii][jj];
        }
    }
}

// ---------------- kernel 3: flash attention, Br=Bc=128, 8x8 tile -------------
// grid (16, 16), 256 threads, 160 KB dynamic smem, 1 CTA/SM.
__global__ void __launch_bounds__(256, 1) flash_kernel(
    const float* __restrict__ Qt, const float* __restrict__ Kt,
    const float* __restrict__ V, const float* __restrict__ P,
    float* __restrict__ O)
{
    extern __shared__ float smf[];
    float* Qts = smf;              // [64][128]  [d][i]
    float* Kts = smf + 8192;       // [64][128]  [d][j]
    float* Vs  = smf + 16384;      // [128][64]  [j][dd]
    float* Pts = smf + 24576;      // [128][128] [j][i], col-quad swizzled

    const int bh = blockIdx.y;
    const int n0 = blockIdx.x << 7;
    const float* Qb = Qt + (size_t)bh * QT_BH;
    const float* Kb = Kt + (size_t)bh * QT_BH;
    const float* Vb = V  + (size_t)bh * NSEQ * DHEAD;
    const float* Pb = P  + (size_t)bh * NSEQ * PLD;

    const int tid = threadIdx.x;
    const int ty  = tid >> 4, tx = tid & 15;

    // --- stage Q once: [d][n0..n0+127] contiguous copy -----------------------
    #pragma unroll
    for (int q = 0; q < 8; q++) {
        int idx = q * 256 + tid;
        int d = idx >> 5, c = (idx & 31) << 2;
        *(float4*)(Qts + d * 128 + c) =
            *(const float4*)(Qb + (size_t)d * NSEQ + n0 + c);
    }

    // --- prefetch K tile 0 into registers -----------------------------------
    float4 kreg[8];
    #pragma unroll
    for (int q = 0; q < 8; q++) {
        int idx = q * 256 + tid;
        int d = idx >> 5, c = (idx & 31) << 2;
        kreg[q] = *(const float4*)(Kb + (size_t)d * NSEQ + c);
    }

    float m_i[8], l_i[8];
    u64 o2[8][2];
    #pragma unroll
    for (int ii = 0; ii < 8; ii++) {
        m_i[ii] = -1e30f; l_i[ii] = 0.0f;
        o2[ii][0] = 0ull; o2[ii][1] = 0ull;
    }

    for (int jt = 0; jt < NSEQ / 128; jt++) {
        const int j0 = jt << 7;

        // stage K from regs, load V (direct copies, conflict-free)
        #pragma unroll
        for (int q = 0; q < 8; q++) {
            int idx = q * 256 + tid;
            int d = idx >> 5, c = (idx & 31) << 2;
            *(float4*)(Kts + d * 128 + c) = kreg[q];
        }
        #pragma unroll
        for (int q = 0; q < 8; q++) {
            int idx = q * 256 + tid;
            int row = idx >> 4, c = (idx & 15) << 2;
            *(float4*)(Vs + row * 64 + c) =
                *(const float4*)(Vb + (size_t)(j0 + row) * DHEAD + c);
        }
        __syncthreads();                                   // A

        // ---- S = Q K^T ------------------------------------------------------
        u64 s2[8][4] = {};
        #pragma unroll 4
        for (int d = 0; d < 64; d++) {
            float4 av0 = *(const float4*)(Qts + d * 128 + (ty << 3));
            float4 av1 = *(const float4*)(Qts + d * 128 + (ty << 3) + 4);
            float4 bv0 = *(const float4*)(Kts + d * 128 + (tx << 3));
            float4 bv1 = *(const float4*)(Kts + d * 128 + (tx << 3) + 4);
            fma8x8(av0, av1, bv0, bv1, s2);
        }

        // prefetch next K tile into regs (hidden under softmax + PV)
        if (jt + 1 < NSEQ / 128) {
            int jn = (jt + 1) << 7;
            #pragma unroll
            for (int q = 0; q < 8; q++) {
                int idx = q * 256 + tid;
                int d = idx >> 5, c = (idx & 31) << 2;
                kreg[q] = *(const float4*)(Kb + (size_t)d * NSEQ + jn + c);
            }
        }

        // ---- bias + online softmax ------------------------------------------
        float s[8][8];
        unpack_acc(s2, s);
        float rowmax[8];
        #pragma unroll
        for (int ii = 0; ii < 8; ii++) {
            int n = n0 + (ty << 3) + ii;
            const float* prow = Pb + (size_t)n * PLD;
            int basei = n - j0 + 512 - (tx << 3);
            rowmax[ii] = -1e30f;
            #pragma unroll
            for (int jj = 0; jj < 8; jj++) {
                int idx = basei - jj;
                idx = idx < 0 ? 0 : (idx > 1024 ? 1024 : idx);
                float v = s[ii][jj] + prow[idx];
                s[ii][jj] = v;
                rowmax[ii] = fmaxf(rowmax[ii], v);
            }
        }
        #pragma unroll
        for (int msk = 1; msk < 16; msk <<= 1)
            #pragma unroll
            for (int ii = 0; ii < 8; ii++)
                rowmax[ii] = fmaxf(rowmax[ii],
                                   __shfl_xor_sync(0xffffffffu, rowmax[ii], msk));

        float rs[8];
        #pragma unroll
        for (int ii = 0; ii < 8; ii++) {
            float mnew = fmaxf(m_i[ii], rowmax[ii]);
            float corr = __expf(m_i[ii] - mnew);
            m_i[ii] = mnew;
            rs[ii] = 0.0f;
            #pragma unroll
            for (int jj = 0; jj < 8; jj++) {
                float p = __expf(s[ii][jj] - mnew);
                s[ii][jj] = p;
                rs[ii] += p;
            }
            l_i[ii] = l_i[ii] * corr + 0.0f;   // corr applied; rs added after shfl
            u64 c2 = dup2(corr);
            mul2(o2[ii][0], c2);
            mul2(o2[ii][1], c2);
        }
        #pragma unroll
        for (int msk = 1; msk < 16; msk <<= 1)
            #pragma unroll
            for (int ii = 0; ii < 8; ii++)
                rs[ii] += __shfl_xor_sync(0xffffffffu, rs[ii], msk);
        #pragma unroll
        for (int ii = 0; ii < 8; ii++) l_i[ii] += rs[ii];

        // ---- stage S transposed into Pts (swizzled col-quads) ---------------
        {
            int sw = (tx & 7) << 2;  // == ((j>>3)&7)<<2 for j = tx*8+jj
            #pragma unroll
            for (int jj = 0; jj < 8; jj++) {
                int j = (tx << 3) + jj;
                int iq0 = ((ty << 1)     ^ sw) << 2;
                int iq1 = (((ty << 1)|1) ^ sw) << 2;
                *(float4*)(Pts + j * 128 + iq0) =
                    make_float4(s[0][jj], s[1][jj], s[2][jj], s[3][jj]);
                *(float4*)(Pts + j * 128 + iq1) =
                    make_float4(s[4][jj], s[5][jj], s[6][jj], s[7][jj]);
            }
        }
        __syncthreads();                                   // B

        // ---- O += P V --------------------------------------------------------
        #pragma unroll 4
        for (int j = 0; j < 128; j++) {
            int sw = ((j >> 3) & 7) << 2;
            float4 av0 = *(const float4*)(Pts + j * 128 + ((((ty << 1))     ^ sw) << 2));
            float4 av1 = *(const float4*)(Pts + j * 128 + ((((ty << 1) | 1) ^ sw) << 2));
            float4 bv  = *(const float4*)(Vs + j * 64 + (tx << 2));
            fma8x4(av0, av1, bv, o2);
        }
        __syncthreads();                                   // C
    }

    // epilogue: normalize, write [b][n][h*64+dd]
    const int b = bh >> 3, head = bh & 7;
    #pragma unroll
    for (int ii = 0; ii < 8; ii++) {
        int n = n0 + (ty << 3) + ii;
        float inv = 1.0f / l_i[ii];
        size_t base = ((size_t)(b * NSEQ + n)) * DIMM + (head << 6) + (tx << 2);
        float4 v;
        unpack2(o2[ii][0], v.x, v.y);
        unpack2(o2[ii][1], v.z, v.w);
        v.x *= inv; v.y *= inv; v.z *= inv; v.w *= inv;
        *(float4*)(O + base) = v;
    }
}

// ---------------- kernel 4: output projection + bias --------------------------
__global__ void __launch_bounds__(256, 2) gemm_out_kernel(
    const float* __restrict__ O, const float* __restrict__ Wo,
    const float* __restrict__ bo, float* __restrict__ out)
{
    __shared__ float Ats[16][128];
    __shared__ float Bs[16][128];

    const int m0 = blockIdx.x << 7;
    const int n0 = blockIdx.y << 7;

    u64 acc[8][4] = {};
    sgemm128(O + (size_t)m0 * DIMM, DIMM, Wo + n0, DIMM, DIMM, acc, Ats, Bs);

    float s[8][8];
    unpack_acc(acc, s);

    const int ty = threadIdx.x >> 4, tx = threadIdx.x & 15;
    const int col = n0 + (tx << 3);
    float4 bias0 = *(const float4*)(bo + col);
    float4 bias1 = *(const float4*)(bo + col + 4);
    #pragma unroll
    for (int ii = 0; ii < 8; ii++) {
        size_t base = (size_t)(m0 + (ty << 3) + ii) * DIMM + col;
        *(float4*)(out + base) = make_float4(s[ii][0] + bias0.x, s[ii][1] + bias0.y,
                                             s[ii][2] + bias0.z, s[ii][3] + bias0.w);
        *(float4*)(out + base + 4) = make_float4(s[ii][4] + bias1.x, s[ii][5] + bias1.y,
                                                 s[ii][6] + bias1.z, s[ii][7] + bias1.w);
    }
}

// ---------------- launch -------------------------------------------------------
extern "C" void kernel_launch(void* const* d_in, const int* in_sizes, int n_in,
                              void* d_out, int out_size)
{
    const float* x    = (const float*)d_in[0];
    const float* Wq   = (const float*)d_in[1];
    const float* Wkv  = (const float*)d_in[2];
    const float* Wo   = (const float*)d_in[3];
    const float* bo   = (const float*)d_in[4];
    const float* rel  = (const float*)d_in[5];
    float* out = (float*)d_out;

    float *Qp, *Qtp, *Ktp, *Vp, *Pp, *Op, *rTp;
    cudaGetSymbolAddress((void**)&Qp,  g_Q);
    cudaGetSymbolAddress((void**)&Qtp, g_Qt);
    cudaGetSymbolAddress((void**)&Ktp, g_Kt);
    cudaGetSymbolAddress((void**)&Vp,  g_V);
    cudaGetSymbolAddress((void**)&Pp,  g_P);
    cudaGetSymbolAddress((void**)&Op,  g_O);
    cudaGetSymbolAddress((void**)&rTp, g_relT);

    cudaFuncSetAttribute(flash_kernel,
                         cudaFuncAttributeMaxDynamicSharedMemorySize, 163840);

    transpose_rel_kernel<<<(DHEAD * RELTLD + 255) / 256, 256>>>(rel, rTp);
    gemm_qkv_kernel<<<dim3(MROWS / 128, 12), 256>>>(x, Wq, Wkv, Qp, Qtp, Ktp, Vp);
    gemm_p_kernel<<<dim3(QROWS / 128, 9), 256>>>(Qp, rTp, Pp);
    flash_kernel<<<dim3(NSEQ / 128, BHDIM), 256, 163840>>>(Qtp, Ktp, Vp, Pp, Op);
    gemm_out_kernel<<<dim3(MROWS / 128, DIMM / 128), 256>>>(Op, Wo, bo, out);
}